// round 9
// baseline (speedup 1.0000x reference)
#include <cuda_runtime.h>
#include <cstdint>
#include <math.h>

#define DIM 128
#define TILE 128
#define BMAX 8192
#define NTMAX 64
#define TPB 4                  // B-tiles per CTA; A tile stays resident
#define LDW 36                 // smem row stride in words (144B): banks (4g+t)%32 distinct

#define QSCALE 24.0f
#define NEG2INV (-2.0f / (QSCALE * QSCALE))

__device__ float g_nsk[BMAX];
__device__ float g_nim[BMAX];
__device__ uint32_t g_ski8[BMAX * 32];                    // s8-packed rows (4/word)
__device__ uint32_t g_imi8[BMAX * 32];
__device__ float g_partial[(size_t)BMAX * NTMAX * 2];     // per (row, bn, wn-half)
__device__ float g_diag[BMAX];                            // exact fp32 diagonal distance
__device__ float g_rowval[BMAX];

static __device__ __forceinline__ uint32_t s2u(const void* p) {
    uint32_t a;
    asm("{ .reg .u64 t; cvta.to.shared.u64 t, %1; cvt.u32.u64 %0, t; }" : "=r"(a) : "l"(p));
    return a;
}
static __device__ __forceinline__ void cpa16(uint32_t dst, const void* src) {
    asm volatile("cp.async.cg.shared.global [%0], [%1], 16;" :: "r"(dst), "l"(src) : "memory");
}
#define CP_COMMIT() asm volatile("cp.async.commit_group;" ::: "memory")
#define CP_WAIT0()  asm volatile("cp.async.wait_group 0;" ::: "memory")
#define CP_WAIT1()  asm volatile("cp.async.wait_group 1;" ::: "memory")

static __device__ __forceinline__ int q8(float x) {
    int q = __float2int_rn(x * QSCALE);
    return max(-127, min(127, q));
}
static __device__ __forceinline__ uint32_t pack_s8x4(float x, float y, float z, float w) {
    return (uint32_t)(q8(x) & 0xff) | ((uint32_t)(q8(y) & 0xff) << 8) |
           ((uint32_t)(q8(z) & 0xff) << 16) | ((uint32_t)(q8(w) & 0xff) << 24);
}
static __device__ __forceinline__ void mma32s8(int* c, const uint32_t* a, const uint32_t* b) {
    asm("mma.sync.aligned.m16n8k32.row.col.s32.s8.s8.s32 "
        "{%0,%1,%2,%3}, {%4,%5,%6,%7}, {%8,%9}, {%0,%1,%2,%3};"
        : "+r"(c[0]), "+r"(c[1]), "+r"(c[2]), "+r"(c[3])
        : "r"(a[0]), "r"(a[1]), "r"(a[2]), "r"(a[3]), "r"(b[0]), "r"(b[1]));
}

// ---------------------------------------------------------------------------
// One warp per row: y=0/1 -> fp32 norms + s8 pack; y=2 -> exact fp32 diag.
// ---------------------------------------------------------------------------
__global__ void prep_kernel(const float* __restrict__ sk,
                            const float* __restrict__ im, int B) {
    int row = (blockIdx.x * blockDim.x + threadIdx.x) >> 5;
    int lane = threadIdx.x & 31;
    if (row >= B) return;
    if (blockIdx.y < 2) {
        const float* src = blockIdx.y ? im : sk;
        float* ndst = blockIdx.y ? g_nim : g_nsk;
        uint32_t* bdst = blockIdx.y ? g_imi8 : g_ski8;
        float4 v = ((const float4*)(src + (size_t)row * DIM))[lane];
        bdst[row * 32 + lane] = pack_s8x4(v.x, v.y, v.z, v.w);
        float s = v.x * v.x + v.y * v.y + v.z * v.z + v.w * v.w;
#pragma unroll
        for (int o = 16; o; o >>= 1) s += __shfl_xor_sync(0xffffffffu, s, o);
        if (lane == 0) ndst[row] = s;
    } else {
        float4 a = ((const float4*)(sk + (size_t)row * DIM))[lane];
        float4 b = ((const float4*)(im + (size_t)row * DIM))[lane];
        float dx = a.x - b.x, dy = a.y - b.y, dz = a.z - b.z, dw = a.w - b.w;
        float s = dx * dx + dy * dy + dz * dz + dw * dw;
#pragma unroll
        for (int o = 16; o; o >>= 1) s += __shfl_xor_sync(0xffffffffu, s, o);
        if (lane == 0) g_diag[row] = sqrtf(s);
    }
}

// ---------------------------------------------------------------------------
// Software-pipelined s8 IMMA + fused distance/exp epilogue (occ 1).
// 8 warps, warp tile 32x64, k-steps of 32. Exact s32 accumulation.
// Epilogue of tile t-1 interleaved (2 chunks per k-step) into mainloop.
// ---------------------------------------------------------------------------
__global__ void __launch_bounds__(256, 1)
dist_mma(int nt) {
    extern __shared__ uint32_t smw[];
    const uint32_t sbase = s2u(smw);
    uint32_t* As = smw;
    const uint32_t NORM_OFF = 3u * 128u * LDW;            // word offset of norm buffer
    float* nsm = (float*)(smw + NORM_OFF);                // 4*128 floats

    const int tid = threadIdx.x;
    const int wid = tid >> 5;
    const int lane = tid & 31;
    const int g = lane >> 2;
    const int t = lane & 3;
    const int wm = wid & 3;        // m-block: 32 rows
    const int wn = wid >> 2;       // n-block: 64 cols

    const int ntg = nt / TPB;
    const int bm = blockIdx.x / ntg;
    const int bn0 = (blockIdx.x % ntg) * TPB;

    // ---- prologue: A, B0, norms (group 0); B1 prefetch (group 1) ----
    {
        const uint32_t* Ag = g_ski8 + (size_t)bm * TILE * 32;
        const uint32_t* Bg = g_imi8 + (size_t)bn0 * TILE * 32;
#pragma unroll
        for (int it = 0; it < 4; it++) {
            int c = it * 256 + tid;          // 0..1023 16B-chunks
            int row = c >> 3, ch = c & 7;
            uint32_t doff = (uint32_t)row * 144 + (uint32_t)ch * 16;
            cpa16(sbase + doff, Ag + row * 32 + ch * 4);
            cpa16(sbase + 128 * LDW * 4 + doff, Bg + row * 32 + ch * 4);
        }
        if (tid < 128)
            cpa16(sbase + NORM_OFF * 4 + (uint32_t)tid * 16, g_nim + (size_t)bn0 * TILE + tid * 4);
        CP_COMMIT();
        const uint32_t* Bg1 = g_imi8 + (size_t)(bn0 + 1) * TILE * 32;
#pragma unroll
        for (int it = 0; it < 4; it++) {
            int c = it * 256 + tid;
            int row = c >> 3, ch = c & 7;
            cpa16(sbase + 2 * 128 * LDW * 4 + (uint32_t)row * 144 + (uint32_t)ch * 16,
                  Bg1 + row * 32 + ch * 4);
        }
        CP_COMMIT();
        CP_WAIT1();
    }
    __syncthreads();

    float nr[2][2];
#pragma unroll
    for (int mt = 0; mt < 2; mt++)
#pragma unroll
        for (int h = 0; h < 2; h++)
            nr[mt][h] = g_nsk[bm * TILE + wm * 32 + mt * 16 + h * 8 + g];

    const int a_base = (wm * 32 + g) * LDW + t;
    const int b_base = (wn * 64 + g) * LDW + t;

    int acc[2][2][8][4];       // [buf][mt][nb][r]  exact s32
    float rs[2][2];

#pragma unroll
    for (int tt = 0; tt <= TPB; tt++) {
        const bool do_main = (tt < TPB);
        const bool do_epi = (tt > 0);
        const int nbuf = tt & 1;
        const int bn_old = bn0 + tt - 1;

        // prefetch B[tt+1] into buffer (tt+1)&1
        if (tt + 1 < TPB) {
            const uint32_t* Bg = g_imi8 + (size_t)(bn0 + tt + 1) * TILE * 32;
            uint32_t dbuf = sbase + (1 + ((tt + 1) & 1)) * 128 * LDW * 4;
#pragma unroll
            for (int it = 0; it < 4; it++) {
                int c = it * 256 + tid;
                int row = c >> 3, ch = c & 7;
                cpa16(dbuf + (uint32_t)row * 144 + (uint32_t)ch * 16, Bg + row * 32 + ch * 4);
            }
            CP_COMMIT();
        }

        int (*accN)[8][4] = acc[nbuf];
        int (*accO)[8][4] = acc[nbuf ^ 1];
        const uint32_t* Bs = smw + (1 + (tt & 1)) * 128 * LDW;

        if (do_main) {
#pragma unroll
            for (int mt = 0; mt < 2; mt++)
#pragma unroll
                for (int nb = 0; nb < 8; nb++)
#pragma unroll
                    for (int r = 0; r < 4; r++) accN[mt][nb][r] = 0;
        }
        if (do_epi) { rs[0][0] = rs[0][1] = rs[1][0] = rs[1][1] = 0.f; }

        // 4 k-steps of 32; 2 epilogue chunks of the previous tile per k-step
#pragma unroll
        for (int ks = 0; ks < 4; ks++) {
            if (do_main) {
                const int ko = ks * 8;       // word offset: 32 bytes = 8 words
                uint32_t a[2][4], b[8][2];
#pragma unroll
                for (int mt = 0; mt < 2; mt++) {
                    int ba = a_base + mt * 16 * LDW + ko;
                    a[mt][0] = As[ba];
                    a[mt][1] = As[ba + 8 * LDW];
                    a[mt][2] = As[ba + 4];
                    a[mt][3] = As[ba + 8 * LDW + 4];
                }
#pragma unroll
                for (int nb = 0; nb < 8; nb++) {
                    int bb = b_base + nb * 8 * LDW + ko;
                    b[nb][0] = Bs[bb];
                    b[nb][1] = Bs[bb + 4];
                }
#pragma unroll
                for (int mt = 0; mt < 2; mt++)
#pragma unroll
                    for (int nb = 0; nb < 8; nb++) mma32s8(accN[mt][nb], a[mt], b[nb]);
            }
            if (do_epi) {
#pragma unroll
                for (int half = 0; half < 2; half++) {
                    const int cb = ks * 2 + half;    // chunk 0..7 of previous tile
                    float2 nc = *(const float2*)&nsm[(tt - 1) * 128 + wn * 64 + cb * 8 + t * 2];
#pragma unroll
                    for (int mt = 0; mt < 2; mt++) {
#pragma unroll
                        for (int h = 0; h < 2; h++) {
                            float base = nr[mt][h];
                            float dot0 = (float)accO[mt][cb][h * 2 + 0];
                            float dot1 = (float)accO[mt][cb][h * 2 + 1];
                            float sq0 = fmaxf(fmaf(dot0, NEG2INV, base + nc.x), 0.f);
                            float sq1 = fmaxf(fmaf(dot1, NEG2INV, base + nc.y), 0.f);
                            float d0, d1, e0, e1;
                            asm("sqrt.approx.f32 %0, %1;" : "=f"(d0) : "f"(sq0));
                            asm("sqrt.approx.f32 %0, %1;" : "=f"(d1) : "f"(sq1));
                            asm("ex2.approx.f32 %0, %1;" : "=f"(e0) : "f"(d0 * -1.4426950408889634f));
                            asm("ex2.approx.f32 %0, %1;" : "=f"(e1) : "f"(d1 * -1.4426950408889634f));
                            rs[mt][h] += e0 + e1;
                        }
                    }
                }
            }
        }

        if (do_epi) {
#pragma unroll
            for (int mt = 0; mt < 2; mt++) {
#pragma unroll
                for (int h = 0; h < 2; h++) {
                    float v = rs[mt][h];
                    v += __shfl_xor_sync(0xffffffffu, v, 1);
                    v += __shfl_xor_sync(0xffffffffu, v, 2);
                    if (t == 0) {
                        int r_local = wm * 32 + mt * 16 + h * 8 + g;
                        g_partial[((size_t)(bm * TILE + r_local) * nt + bn_old) * 2 + wn] = v;
                    }
                }
            }
        }

        if (do_main) {
            CP_WAIT0();
            __syncthreads();
        }
    }
}

// ---------------------------------------------------------------------------
// Per-row: log(sum of 2*nt partials) + exact diag (fixed order, deterministic)
// ---------------------------------------------------------------------------
__global__ void rows_kernel(int B, int nt) {
    int i = blockIdx.x * blockDim.x + threadIdx.x;
    if (i >= B) return;
    float s = 0.f;
    const float* p = g_partial + (size_t)i * nt * 2;
    for (int t = 0; t < 2 * nt; t++) s += p[t];
    g_rowval[i] = logf(s) + g_diag[i];
}

__global__ void final_kernel(float* __restrict__ out, int B, int out_size) {
    __shared__ float sm[1024];
    int tid = threadIdx.x;
    float s = 0.f;
    for (int i = tid; i < B; i += 1024) s += g_rowval[i];
    sm[tid] = s;
    __syncthreads();
    for (int o = 512; o; o >>= 1) {
        if (tid < o) sm[tid] += sm[tid + o];
        __syncthreads();
    }
    if (tid == 0) {
        float loss = sm[0] / (float)B;
        for (int i = 0; i < out_size; i++) out[i] = loss;
    }
}

extern "C" void kernel_launch(void* const* d_in, const int* in_sizes, int n_in,
                              void* d_out, int out_size) {
    const float* sk = (const float*)d_in[0];
    const float* im = (const float*)d_in[1];
    float* out = (float*)d_out;

    int B = in_sizes[0] / DIM;   // 8192
    int nt = B / TILE;           // 64

    prep_kernel<<<dim3(B / 8, 3), 256>>>(sk, im, B);

    static const int SMEM_BYTES = (3 * 128 * LDW + 4 * 128) * 4;   // 57344
    cudaFuncSetAttribute(dist_mma, cudaFuncAttributeMaxDynamicSharedMemorySize, SMEM_BYTES);
    int ncta = nt * (nt / TPB);  // 1024
    dist_mma<<<ncta, 256, SMEM_BYTES>>>(nt);

    rows_kernel<<<(B + 255) / 256, 256>>>(B, nt);
    final_kernel<<<1, 1024>>>(out, B, out_size);
}

// round 10
// speedup vs baseline: 1.4108x; 1.4108x over previous
#include <cuda_runtime.h>
#include <cstdint>
#include <math.h>

#define DIM 128
#define BMAX 8192
#define TPB 8                  // 64-wide B-tiles per CTA; A tile stays resident
#define LDW 68                 // smem row stride in words (272B): banks (4g+t)%32 distinct

// smem word offsets
#define A_WORDS   (128 * LDW)          // 8704
#define B_WORDS   (64 * LDW)           // 4352
#define NORM_OFF  (A_WORDS + 2 * B_WORDS)   // 17408
#define SMEM_WORDS (NORM_OFF + 512)    // 17920 -> 71680 bytes

__device__ float g_nsk[BMAX];
__device__ float g_nim[BMAX];
__device__ uint32_t g_skbf[BMAX * 64];                    // bf16x2-packed rows
__device__ uint32_t g_imbf[BMAX * 64];
__device__ float g_partial[(size_t)BMAX * 128 * 2];       // per (row, bn64, wn-half)
__device__ float g_diag[BMAX];                            // exact fp32 diagonal distance
__device__ float g_rowval[BMAX];

static __device__ __forceinline__ uint32_t s2u(const void* p) {
    uint32_t a;
    asm("{ .reg .u64 t; cvta.to.shared.u64 t, %1; cvt.u32.u64 %0, t; }" : "=r"(a) : "l"(p));
    return a;
}
static __device__ __forceinline__ void cpa16(uint32_t dst, const void* src) {
    asm volatile("cp.async.cg.shared.global [%0], [%1], 16;" :: "r"(dst), "l"(src) : "memory");
}
#define CP_COMMIT() asm volatile("cp.async.commit_group;" ::: "memory")
#define CP_WAIT0()  asm volatile("cp.async.wait_group 0;" ::: "memory")
#define CP_WAIT1()  asm volatile("cp.async.wait_group 1;" ::: "memory")

static __device__ __forceinline__ uint32_t packbf(float lo, float hi) {
    uint32_t r;
    asm("cvt.rn.bf16x2.f32 %0, %1, %2;" : "=r"(r) : "f"(hi), "f"(lo));
    return r;
}
static __device__ __forceinline__ void mma16(float* c, const uint32_t* a, const uint32_t* b) {
    asm("mma.sync.aligned.m16n8k16.row.col.f32.bf16.bf16.f32 "
        "{%0,%1,%2,%3}, {%4,%5,%6,%7}, {%8,%9}, {%0,%1,%2,%3};"
        : "+f"(c[0]), "+f"(c[1]), "+f"(c[2]), "+f"(c[3])
        : "r"(a[0]), "r"(a[1]), "r"(a[2]), "r"(a[3]), "r"(b[0]), "r"(b[1]));
}

// ---------------------------------------------------------------------------
// One warp per row: y=0/1 -> fp32 norms + bf16 pack; y=2 -> exact fp32 diag.
// ---------------------------------------------------------------------------
__global__ void prep_kernel(const float* __restrict__ sk,
                            const float* __restrict__ im, int B) {
    int row = (blockIdx.x * blockDim.x + threadIdx.x) >> 5;
    int lane = threadIdx.x & 31;
    if (row >= B) return;
    if (blockIdx.y < 2) {
        const float* src = blockIdx.y ? im : sk;
        float* ndst = blockIdx.y ? g_nim : g_nsk;
        uint32_t* bdst = blockIdx.y ? g_imbf : g_skbf;
        float4 v = ((const float4*)(src + (size_t)row * DIM))[lane];
        bdst[row * 64 + lane * 2]     = packbf(v.x, v.y);
        bdst[row * 64 + lane * 2 + 1] = packbf(v.z, v.w);
        float s = v.x * v.x + v.y * v.y + v.z * v.z + v.w * v.w;
#pragma unroll
        for (int o = 16; o; o >>= 1) s += __shfl_xor_sync(0xffffffffu, s, o);
        if (lane == 0) ndst[row] = s;
    } else {
        float4 a = ((const float4*)(sk + (size_t)row * DIM))[lane];
        float4 b = ((const float4*)(im + (size_t)row * DIM))[lane];
        float dx = a.x - b.x, dy = a.y - b.y, dz = a.z - b.z, dw = a.w - b.w;
        float s = dx * dx + dy * dy + dz * dz + dw * dw;
#pragma unroll
        for (int o = 16; o; o >>= 1) s += __shfl_xor_sync(0xffffffffu, s, o);
        if (lane == 0) g_diag[row] = sqrtf(s);
    }
}

// ---------------------------------------------------------------------------
// bf16 MMA + fused distance/exp epilogue, CTA tile 128x64, occupancy 2.
// 8 warps, warp tile 32x32. Epilogue of tile t-1 interleaved per k-step.
// occ 2 hides each CTA's prologue / tail epilogue under its co-CTA's mainloop.
// ---------------------------------------------------------------------------
__global__ void __launch_bounds__(256, 2)
dist_mma(int nt64) {
    extern __shared__ uint32_t smw[];
    const uint32_t sbase = s2u(smw);
    uint32_t* As = smw;
    float* nsm = (float*)(smw + NORM_OFF);     // 8 tiles x 64 floats

    const int tid = threadIdx.x;
    const int wid = tid >> 5;
    const int lane = tid & 31;
    const int g = lane >> 2;
    const int t = lane & 3;
    const int wm = wid & 3;        // m-block: 32 rows
    const int wn = wid >> 2;       // n-block: 32 cols (0..1)

    const int ntg = nt64 / TPB;                   // 16
    const int bm = blockIdx.x / ntg;
    const int bn0 = (blockIdx.x % ntg) * TPB;

    // ---- prologue: A(128x128), B0(64x128), norms (group 0); B1 (group 1) ----
    {
        const uint32_t* Ag = g_skbf + (size_t)bm * 128 * 64;
        const uint32_t* Bg = g_imbf + (size_t)bn0 * 64 * 64;
#pragma unroll
        for (int it = 0; it < 8; it++) {          // A: 2048 16B-chunks
            int c = it * 256 + tid;
            int row = c >> 4, ch = c & 15;
            cpa16(sbase + (uint32_t)row * 272 + (uint32_t)ch * 16, Ag + row * 64 + ch * 4);
        }
#pragma unroll
        for (int it = 0; it < 4; it++) {          // B0: 1024 chunks
            int c = it * 256 + tid;
            int row = c >> 4, ch = c & 15;
            cpa16(sbase + A_WORDS * 4 + (uint32_t)row * 272 + (uint32_t)ch * 16,
                  Bg + row * 64 + ch * 4);
        }
        if (tid < 128)                            // all 8 tiles' norms (512 floats)
            cpa16(sbase + NORM_OFF * 4 + (uint32_t)tid * 16, g_nim + (size_t)bn0 * 64 + tid * 4);
        CP_COMMIT();
        const uint32_t* Bg1 = g_imbf + (size_t)(bn0 + 1) * 64 * 64;
#pragma unroll
        for (int it = 0; it < 4; it++) {
            int c = it * 256 + tid;
            int row = c >> 4, ch = c & 15;
            cpa16(sbase + (A_WORDS + B_WORDS) * 4 + (uint32_t)row * 272 + (uint32_t)ch * 16,
                  Bg1 + row * 64 + ch * 4);
        }
        CP_COMMIT();
        CP_WAIT1();
    }
    __syncthreads();

    float nr[2][2];
#pragma unroll
    for (int mt = 0; mt < 2; mt++)
#pragma unroll
        for (int h = 0; h < 2; h++)
            nr[mt][h] = g_nsk[bm * 128 + wm * 32 + mt * 16 + h * 8 + g];

    const int a_base = (wm * 32 + g) * LDW + t;
    const int b_base = (wn * 32 + g) * LDW + t;

    float acc[2][2][4][4];     // [buf][mt][nb][r]
    float rs[2][2];

#pragma unroll
    for (int tt = 0; tt <= TPB; tt++) {
        const bool do_main = (tt < TPB);
        const bool do_epi = (tt > 0);
        const int nbuf = tt & 1;
        const int bn_old = bn0 + tt - 1;

        // prefetch B[tt+1] into the other buffer
        if (tt + 1 < TPB) {
            const uint32_t* Bg = g_imbf + (size_t)(bn0 + tt + 1) * 64 * 64;
            uint32_t dbuf = sbase + (A_WORDS + ((tt + 1) & 1) * B_WORDS) * 4;
#pragma unroll
            for (int it = 0; it < 4; it++) {
                int c = it * 256 + tid;
                int row = c >> 4, ch = c & 15;
                cpa16(dbuf + (uint32_t)row * 272 + (uint32_t)ch * 16, Bg + row * 64 + ch * 4);
            }
            CP_COMMIT();
        }

        float (*accN)[4][4] = acc[nbuf];
        float (*accO)[4][4] = acc[nbuf ^ 1];
        const uint32_t* Bs = smw + A_WORDS + (tt & 1) * B_WORDS;

        if (do_main) {
#pragma unroll
            for (int mt = 0; mt < 2; mt++)
#pragma unroll
                for (int nb = 0; nb < 4; nb++)
#pragma unroll
                    for (int r = 0; r < 4; r++) accN[mt][nb][r] = 0.f;
        }
        if (do_epi) { rs[0][0] = rs[0][1] = rs[1][0] = rs[1][1] = 0.f; }

        // 8 k-steps of 16; one (mt,nb) epilogue chunk of the previous tile per k-step
#pragma unroll
        for (int ks = 0; ks < 8; ks++) {
            if (do_main) {
                const int ko = ks * 8;       // 16 bf16 = 8 words
                uint32_t a[2][4], b[4][2];
#pragma unroll
                for (int mt = 0; mt < 2; mt++) {
                    int ba = a_base + mt * 16 * LDW + ko;
                    a[mt][0] = As[ba];
                    a[mt][1] = As[ba + 8 * LDW];
                    a[mt][2] = As[ba + 4];
                    a[mt][3] = As[ba + 8 * LDW + 4];
                }
#pragma unroll
                for (int nb = 0; nb < 4; nb++) {
                    int bb = b_base + nb * 8 * LDW + ko;
                    b[nb][0] = Bs[bb];
                    b[nb][1] = Bs[bb + 4];
                }
#pragma unroll
                for (int mt = 0; mt < 2; mt++)
#pragma unroll
                    for (int nb = 0; nb < 4; nb++) mma16(accN[mt][nb], a[mt], b[nb]);
            }
            if (do_epi) {
                const int emt = ks >> 2;            // 0..1
                const int enb = ks & 3;             // 0..3
                float2 nc = *(const float2*)&nsm[(tt - 1) * 64 + wn * 32 + enb * 8 + t * 2];
#pragma unroll
                for (int h = 0; h < 2; h++) {
                    float base = nr[emt][h];
                    float sq0 = fmaxf(fmaf(-2.f, accO[emt][enb][h * 2 + 0], base + nc.x), 0.f);
                    float sq1 = fmaxf(fmaf(-2.f, accO[emt][enb][h * 2 + 1], base + nc.y), 0.f);
                    float d0, d1, e0, e1;
                    asm("sqrt.approx.f32 %0, %1;" : "=f"(d0) : "f"(sq0));
                    asm("sqrt.approx.f32 %0, %1;" : "=f"(d1) : "f"(sq1));
                    asm("ex2.approx.f32 %0, %1;" : "=f"(e0) : "f"(d0 * -1.4426950408889634f));
                    asm("ex2.approx.f32 %0, %1;" : "=f"(e1) : "f"(d1 * -1.4426950408889634f));
                    rs[emt][h] += e0 + e1;
                }
            }
        }

        if (do_epi) {
#pragma unroll
            for (int mt = 0; mt < 2; mt++) {
#pragma unroll
                for (int h = 0; h < 2; h++) {
                    float v = rs[mt][h];
                    v += __shfl_xor_sync(0xffffffffu, v, 1);
                    v += __shfl_xor_sync(0xffffffffu, v, 2);
                    if (t == 0) {
                        int r_local = wm * 32 + mt * 16 + h * 8 + g;
                        g_partial[((size_t)(bm * 128 + r_local) * nt64 + bn_old) * 2 + wn] = v;
                    }
                }
            }
        }

        if (do_main) {
            CP_WAIT0();
            __syncthreads();
        }
    }
}

// ---------------------------------------------------------------------------
// Per-row: log(sum of 2*nt64 partials) + exact diag (fixed order)
// ---------------------------------------------------------------------------
__global__ void rows_kernel(int B, int nt64) {
    int i = blockIdx.x * blockDim.x + threadIdx.x;
    if (i >= B) return;
    float s = 0.f;
    const float* p = g_partial + (size_t)i * nt64 * 2;
    for (int t = 0; t < 2 * nt64; t++) s += p[t];
    g_rowval[i] = logf(s) + g_diag[i];
}

__global__ void final_kernel(float* __restrict__ out, int B, int out_size) {
    __shared__ float sm[1024];
    int tid = threadIdx.x;
    float s = 0.f;
    for (int i = tid; i < B; i += 1024) s += g_rowval[i];
    sm[tid] = s;
    __syncthreads();
    for (int o = 512; o; o >>= 1) {
        if (tid < o) sm[tid] += sm[tid + o];
        __syncthreads();
    }
    if (tid == 0) {
        float loss = sm[0] / (float)B;
        for (int i = 0; i < out_size; i++) out[i] = loss;
    }
}

extern "C" void kernel_launch(void* const* d_in, const int* in_sizes, int n_in,
                              void* d_out, int out_size) {
    const float* sk = (const float*)d_in[0];
    const float* im = (const float*)d_in[1];
    float* out = (float*)d_out;

    int B = in_sizes[0] / DIM;   // 8192
    int nt64 = B / 64;           // 128

    prep_kernel<<<dim3(B / 8, 3), 256>>>(sk, im, B);

    static const int SMEM_BYTES = SMEM_WORDS * 4;   // 71680
    cudaFuncSetAttribute(dist_mma, cudaFuncAttributeMaxDynamicSharedMemorySize, SMEM_BYTES);
    int ncta = (B / 128) * (nt64 / TPB);  // 64 * 16 = 1024
    dist_mma<<<ncta, 256, SMEM_BYTES>>>(nt64);

    rows_kernel<<<(B + 255) / 256, 256>>>(B, nt64);
    final_kernel<<<1, 1024>>>(out, B, out_size);
}

// round 11
// speedup vs baseline: 1.5857x; 1.1239x over previous
#include <cuda_runtime.h>
#include <cuda_fp16.h>
#include <cstdint>
#include <math.h>

#define DIM 128
#define TILE 128
#define BMAX 8192
#define NTMAX 64
#define TPB 4                  // B-tiles per CTA; A tile stays resident
#define LDW 68                 // smem row stride in words (272B): banks (4g+t)%32 distinct

__device__ float g_nsk[BMAX];
__device__ float g_nim[BMAX];
__device__ uint32_t g_skh[BMAX * 64];                     // f16x2-packed rows
__device__ uint32_t g_imh[BMAX * 64];
__device__ float g_partial[(size_t)BMAX * NTMAX * 2];     // per (row, bn, wn-half)
__device__ float g_diag[BMAX];                            // exact fp32 diagonal distance
__device__ float g_bsum[32];                              // block partial sums

static __device__ __forceinline__ uint32_t s2u(const void* p) {
    uint32_t a;
    asm("{ .reg .u64 t; cvta.to.shared.u64 t, %1; cvt.u32.u64 %0, t; }" : "=r"(a) : "l"(p));
    return a;
}
static __device__ __forceinline__ void cpa16(uint32_t dst, const void* src) {
    asm volatile("cp.async.cg.shared.global [%0], [%1], 16;" :: "r"(dst), "l"(src) : "memory");
}
#define CP_COMMIT() asm volatile("cp.async.commit_group;" ::: "memory")
#define CP_WAIT0()  asm volatile("cp.async.wait_group 0;" ::: "memory")
#define CP_WAIT1()  asm volatile("cp.async.wait_group 1;" ::: "memory")

// f16-accumulate legacy HMMA: 2-reg packed accumulator
static __device__ __forceinline__ void mma16h(uint32_t* c, const uint32_t* a, const uint32_t* b) {
    asm("mma.sync.aligned.m16n8k16.row.col.f16.f16.f16.f16 "
        "{%0,%1}, {%2,%3,%4,%5}, {%6,%7}, {%0,%1};"
        : "+r"(c[0]), "+r"(c[1])
        : "r"(a[0]), "r"(a[1]), "r"(a[2]), "r"(a[3]), "r"(b[0]), "r"(b[1]));
}

// ---------------------------------------------------------------------------
// One warp per row: y=0/1 -> fp32 norms + f16 pack; y=2 -> exact fp32 diag.
// ---------------------------------------------------------------------------
__global__ void prep_kernel(const float* __restrict__ sk,
                            const float* __restrict__ im, int B) {
    int row = (blockIdx.x * blockDim.x + threadIdx.x) >> 5;
    int lane = threadIdx.x & 31;
    if (row >= B) return;
    if (blockIdx.y < 2) {
        const float* src = blockIdx.y ? im : sk;
        float* ndst = blockIdx.y ? g_nim : g_nsk;
        uint32_t* bdst = blockIdx.y ? g_imh : g_skh;
        float4 v = ((const float4*)(src + (size_t)row * DIM))[lane];
        __half2 h0 = __floats2half2_rn(v.x, v.y);
        __half2 h1 = __floats2half2_rn(v.z, v.w);
        bdst[row * 64 + lane * 2]     = *(uint32_t*)&h0;
        bdst[row * 64 + lane * 2 + 1] = *(uint32_t*)&h1;
        float s = v.x * v.x + v.y * v.y + v.z * v.z + v.w * v.w;
#pragma unroll
        for (int o = 16; o; o >>= 1) s += __shfl_xor_sync(0xffffffffu, s, o);
        if (lane == 0) ndst[row] = s;
    } else {
        float4 a = ((const float4*)(sk + (size_t)row * DIM))[lane];
        float4 b = ((const float4*)(im + (size_t)row * DIM))[lane];
        float dx = a.x - b.x, dy = a.y - b.y, dz = a.z - b.z, dw = a.w - b.w;
        float s = dx * dx + dy * dy + dz * dz + dw * dw;
#pragma unroll
        for (int o = 16; o; o >>= 1) s += __shfl_xor_sync(0xffffffffu, s, o);
        if (lane == 0) g_diag[row] = sqrtf(s);
    }
}

// ---------------------------------------------------------------------------
// Software-pipelined f16 MMA (f16 accumulate) + fused distance/exp epilogue.
// 8 warps, warp tile 32x64. Epilogue of tile t-1 interleaved per k-step
// (R5 structure). Accumulators are packed f16x2 -> 2 regs per MMA.
// ---------------------------------------------------------------------------
__global__ void __launch_bounds__(256, 1)
dist_mma(int nt) {
    extern __shared__ uint32_t smw[];
    const uint32_t sbase = s2u(smw);
    uint32_t* As = smw;
    const uint32_t NORM_OFF = 3u * 128u * LDW;            // word offset of norm buffer
    float* nsm = (float*)(smw + NORM_OFF);                // 4*128 floats

    const int tid = threadIdx.x;
    const int wid = tid >> 5;
    const int lane = tid & 31;
    const int g = lane >> 2;
    const int t = lane & 3;
    const int wm = wid & 3;        // m-block: 32 rows
    const int wn = wid >> 2;       // n-block: 64 cols

    const int ntg = nt / TPB;
    const int bm = blockIdx.x / ntg;
    const int bn0 = (blockIdx.x % ntg) * TPB;

    // ---- prologue: A, B0, norms (group 0); B1 prefetch (group 1) ----
    {
        const uint32_t* Ag = g_skh + (size_t)bm * TILE * 64;
        const uint32_t* Bg = g_imh + (size_t)bn0 * TILE * 64;
#pragma unroll
        for (int it = 0; it < 8; it++) {
            int c = it * 256 + tid;          // 0..2047 16B-chunks
            int row = c >> 4, ch = c & 15;
            uint32_t doff = (uint32_t)row * 272 + (uint32_t)ch * 16;
            cpa16(sbase + doff, Ag + row * 64 + ch * 4);
            cpa16(sbase + 128 * LDW * 4 + doff, Bg + row * 64 + ch * 4);
        }
        if (tid < 128)
            cpa16(sbase + NORM_OFF * 4 + (uint32_t)tid * 16, g_nim + (size_t)bn0 * TILE + tid * 4);
        CP_COMMIT();
        const uint32_t* Bg1 = g_imh + (size_t)(bn0 + 1) * TILE * 64;
#pragma unroll
        for (int it = 0; it < 8; it++) {
            int c = it * 256 + tid;
            int row = c >> 4, ch = c & 15;
            cpa16(sbase + 2 * 128 * LDW * 4 + (uint32_t)row * 272 + (uint32_t)ch * 16,
                  Bg1 + row * 64 + ch * 4);
        }
        CP_COMMIT();
        CP_WAIT1();
    }
    __syncthreads();

    float nr[2][2];
#pragma unroll
    for (int mt = 0; mt < 2; mt++)
#pragma unroll
        for (int h = 0; h < 2; h++)
            nr[mt][h] = g_nsk[bm * TILE + wm * 32 + mt * 16 + h * 8 + g];

    const int a_base = (wm * 32 + g) * LDW + t;
    const int b_base = (wn * 64 + g) * LDW + t;

    uint32_t acc[2][2][8][2];      // [buf][mt][nb][h]  packed f16x2
    float rs[2][2];

#pragma unroll
    for (int tt = 0; tt <= TPB; tt++) {
        const bool do_main = (tt < TPB);
        const bool do_epi = (tt > 0);
        const int nbuf = tt & 1;
        const int bn_old = bn0 + tt - 1;

        // prefetch B[tt+1] into buffer (tt+1)&1
        if (tt + 1 < TPB) {
            const uint32_t* Bg = g_imh + (size_t)(bn0 + tt + 1) * TILE * 64;
            uint32_t dbuf = sbase + (1 + ((tt + 1) & 1)) * 128 * LDW * 4;
#pragma unroll
            for (int it = 0; it < 8; it++) {
                int c = it * 256 + tid;
                int row = c >> 4, ch = c & 15;
                cpa16(dbuf + (uint32_t)row * 272 + (uint32_t)ch * 16, Bg + row * 64 + ch * 4);
            }
            CP_COMMIT();
        }

        uint32_t (*accN)[8][2] = acc[nbuf];
        uint32_t (*accO)[8][2] = acc[nbuf ^ 1];
        const uint32_t* Bs = smw + (1 + (tt & 1)) * 128 * LDW;

        if (do_main) {
#pragma unroll
            for (int mt = 0; mt < 2; mt++)
#pragma unroll
                for (int nb = 0; nb < 8; nb++) {
                    accN[mt][nb][0] = 0u;
                    accN[mt][nb][1] = 0u;
                }
        }
        if (do_epi) { rs[0][0] = rs[0][1] = rs[1][0] = rs[1][1] = 0.f; }

        // 8 k-steps of 16; 1 epilogue chunk (nb=ks) of the previous tile per step
#pragma unroll
        for (int ks = 0; ks < 8; ks++) {
            if (do_main) {
                const int ko = ks * 8;       // 16 f16 = 8 words
                uint32_t a[2][4], b[8][2];
#pragma unroll
                for (int mt = 0; mt < 2; mt++) {
                    int ba = a_base + mt * 16 * LDW + ko;
                    a[mt][0] = As[ba];
                    a[mt][1] = As[ba + 8 * LDW];
                    a[mt][2] = As[ba + 4];
                    a[mt][3] = As[ba + 8 * LDW + 4];
                }
#pragma unroll
                for (int nb = 0; nb < 8; nb++) {
                    int bb = b_base + nb * 8 * LDW + ko;
                    b[nb][0] = Bs[bb];
                    b[nb][1] = Bs[bb + 4];
                }
#pragma unroll
                for (int mt = 0; mt < 2; mt++)
#pragma unroll
                    for (int nb = 0; nb < 8; nb++) mma16h(accN[mt][nb], a[mt], b[nb]);
            }
            if (do_epi) {
                float2 nc = *(const float2*)&nsm[(tt - 1) * 128 + wn * 64 + ks * 8 + t * 2];
#pragma unroll
                for (int mt = 0; mt < 2; mt++) {
#pragma unroll
                    for (int h = 0; h < 2; h++) {
                        float2 dot = __half22float2(*(__half2*)&accO[mt][ks][h]);
                        float base = nr[mt][h];
                        float sq0 = fmaxf(fmaf(-2.f, dot.x, base + nc.x), 0.f);
                        float sq1 = fmaxf(fmaf(-2.f, dot.y, base + nc.y), 0.f);
                        float d0, d1, e0, e1;
                        asm("sqrt.approx.f32 %0, %1;" : "=f"(d0) : "f"(sq0));
                        asm("sqrt.approx.f32 %0, %1;" : "=f"(d1) : "f"(sq1));
                        asm("ex2.approx.f32 %0, %1;" : "=f"(e0) : "f"(d0 * -1.4426950408889634f));
                        asm("ex2.approx.f32 %0, %1;" : "=f"(e1) : "f"(d1 * -1.4426950408889634f));
                        rs[mt][h] += e0 + e1;
                    }
                }
            }
        }

        if (do_epi) {
#pragma unroll
            for (int mt = 0; mt < 2; mt++) {
#pragma unroll
                for (int h = 0; h < 2; h++) {
                    float v = rs[mt][h];
                    v += __shfl_xor_sync(0xffffffffu, v, 1);
                    v += __shfl_xor_sync(0xffffffffu, v, 2);
                    if (t == 0) {
                        int r_local = wm * 32 + mt * 16 + h * 8 + g;
                        g_partial[((size_t)(bm * TILE + r_local) * nt + bn_old) * 2 + wn] = v;
                    }
                }
            }
        }

        if (do_main) {
            CP_WAIT0();
            __syncthreads();
        }
    }
}

// ---------------------------------------------------------------------------
// Per-row lse + exact diag, then block-level partial sum (deterministic).
// 32 blocks x 256 threads; each block reduces its 256 rows.
// ---------------------------------------------------------------------------
__global__ void rows_kernel(int B, int nt) {
    __shared__ float sm[256];
    int i = blockIdx.x * blockDim.x + threadIdx.x;
    float rv = 0.f;
    if (i < B) {
        float s = 0.f;
        const float* p = g_partial + (size_t)i * nt * 2;
        for (int t = 0; t < 2 * nt; t++) s += p[t];
        rv = logf(s) + g_diag[i];
    }
    sm[threadIdx.x] = rv;
    __syncthreads();
    for (int o = 128; o; o >>= 1) {
        if (threadIdx.x < o) sm[threadIdx.x] += sm[threadIdx.x + o];
        __syncthreads();
    }
    if (threadIdx.x == 0) g_bsum[blockIdx.x] = sm[0];
}

__global__ void final_kernel(float* __restrict__ out, int B, int nblk, int out_size) {
    if (threadIdx.x == 0) {
        float s = 0.f;
        for (int i = 0; i < nblk; i++) s += g_bsum[i];
        float loss = s / (float)B;
        for (int i = 0; i < out_size; i++) out[i] = loss;
    }
}

extern "C" void kernel_launch(void* const* d_in, const int* in_sizes, int n_in,
                              void* d_out, int out_size) {
    const float* sk = (const float*)d_in[0];
    const float* im = (const float*)d_in[1];
    float* out = (float*)d_out;

    int B = in_sizes[0] / DIM;   // 8192
    int nt = B / TILE;           // 64

    prep_kernel<<<dim3(B / 8, 3), 256>>>(sk, im, B);

    static const int SMEM_BYTES = (3 * 128 * LDW + 4 * 128) * 4;   // 106496
    cudaFuncSetAttribute(dist_mma, cudaFuncAttributeMaxDynamicSharedMemorySize, SMEM_BYTES);
    int ncta = nt * (nt / TPB);  // 1024
    dist_mma<<<ncta, 256, SMEM_BYTES>>>(nt);

    int nblk = (B + 255) / 256;  // 32
    rows_kernel<<<nblk, 256>>>(B, nt);
    final_kernel<<<1, 32>>>(out, B, nblk, out_size);
}